// round 11
// baseline (speedup 1.0000x reference)
#include <cuda_runtime.h>
#include <cuda_bf16.h>
#include <cstdint>

// Problem constants
#define Bb 2048
#define Tt 2048
#define S  16  // SMEM ring stages / prefetch distance (buffers padded by S steps)
// F=8, U=3, 3U=9

// Scratch: __device__ globals (allocation-free rule). Padded by S steps so
// ALL pipeline loads are unconditional and in-bounds.
__device__ float4 g_bufZ[(size_t)(Tt + S) * Bb];  // {.5*xz0,.5*xz1,.5*xz2, .5*mask}
__device__ float4 g_bufR[(size_t)(Tt + S) * Bb];  // {.5*xr0,.5*xr1,.5*xr2, 0}
__device__ float4 g_bufH[(size_t)(Tt + S) * Bb];  // {xh0, xh1, xh2, 0}
__device__ float  g_outT[(size_t)Tt * Bb];        // out in [t][b] layout

typedef unsigned long long u64;
typedef unsigned int u32;

// HW tanh (sm_75+): 1 MUFU op, rel err ~2^-11
__device__ __forceinline__ float tanh_fast(float x) {
    float y;
    asm("tanh.approx.f32 %0, %1;" : "=f"(y) : "f"(x));
    return y;
}

// f32x2 packed helpers (Blackwell FFMA2 — ptxas never auto-fuses from C++)
__device__ __forceinline__ u64 pk(float lo, float hi) {
    u64 r;
    asm("mov.b64 %0, {%1,%2};" : "=l"(r) : "f"(lo), "f"(hi));
    return r;
}
__device__ __forceinline__ void upk(u64 v, float& lo, float& hi) {
    asm("mov.b64 {%0,%1}, %2;" : "=f"(lo), "=f"(hi) : "l"(v));
}
__device__ __forceinline__ u64 fma2(u64 a, u64 b, u64 c) {
    u64 d;
    asm("fma.rn.f32x2 %0, %1, %2, %3;" : "=l"(d) : "l"(a), "l"(b), "l"(c));
    return d;
}
__device__ __forceinline__ u64 mul2(u64 a, u64 b) {
    u64 d;
    asm("mul.rn.f32x2 %0, %1, %2;" : "=l"(d) : "l"(a), "l"(b));
    return d;
}

// cp.async 16B: completion via commit-group counters (NOT register SB slots)
__device__ __forceinline__ void cp16(u32 smem_dst, const void* gsrc) {
    asm volatile("cp.async.cg.shared.global [%0], [%1], 16;"
                 :: "r"(smem_dst), "l"(gsrc) : "memory");
}
__device__ __forceinline__ void cp_commit() {
    asm volatile("cp.async.commit_group;" ::: "memory");
}
template <int N>
__device__ __forceinline__ void cp_wait() {
    asm volatile("cp.async.wait_group %0;" :: "n"(N) : "memory");
}

__device__ __forceinline__ u32 smem_u32(const void* p) {
    u32 a;
    asm("{ .reg .u64 t; cvta.to.shared.u64 t, %1; cvt.u32.u64 %0, t; }"
        : "=r"(a) : "l"(p));
    return a;
}

// ---------------------------------------------------------------------------
// Kernel A: input projection + mask -> [t][b]-major packed tiles.
// z/r pre-activations stored PRE-HALVED; mask stored as 0.5*m.
// ---------------------------------------------------------------------------
__global__ void __launch_bounds__(256) prep_kernel(
    const float* __restrict__ x,       // [B][T][8]
    const float* __restrict__ kern,    // [8][9]
    const float* __restrict__ bias_i,  // [9]
    const float* __restrict__ bias_r)  // [9]
{
    const int b  = blockIdx.x * 256 + threadIdx.x;
    const int t0 = blockIdx.y * 8;

    float bs[9];
#pragma unroll
    for (int j = 0; j < 9; j++) bs[j] = __ldg(bias_i + j) + __ldg(bias_r + j);
    float wv[8][9];
#pragma unroll
    for (int f = 0; f < 8; f++)
#pragma unroll
        for (int j = 0; j < 9; j++) wv[f][j] = __ldg(kern + f * 9 + j);

    const float4* x4 = reinterpret_cast<const float4*>(x) + (size_t)b * (Tt * 2);

#pragma unroll
    for (int i = 0; i < 8; i++) {
        const int t = t0 + i;
        float4 a = __ldg(x4 + (size_t)t * 2);
        float4 c = __ldg(x4 + (size_t)t * 2 + 1);
        float xf[8] = {a.x, a.y, a.z, a.w, c.x, c.y, c.z, c.w};

        float m = 0.0f;
#pragma unroll
        for (int f = 0; f < 8; f++)
            if (xf[f] != 0.0f) m = 0.5f;   // store 0.5*mask

        float acc[9];
#pragma unroll
        for (int j = 0; j < 9; j++) {
            float s = bs[j];
#pragma unroll
            for (int f = 0; f < 8; f++) s = fmaf(xf[f], wv[f][j], s);
            acc[j] = s;
        }

        const size_t o = (size_t)t * Bb + b;
        g_bufZ[o] = make_float4(0.5f * acc[0], 0.5f * acc[1], 0.5f * acc[2], m);
        g_bufR[o] = make_float4(0.5f * acc[3], 0.5f * acc[4], 0.5f * acc[5], 0.0f);
        g_bufH[o] = make_float4(acc[6], acc[7], acc[8], 0.0f);
    }
}

// ---------------------------------------------------------------------------
// Kernel B: sequential GRU scan, 64 blocks x 32 threads = 2048 lanes.
// cp.async SMEM ring pipeline, depth S=16: wait_group slack of S-2=14 groups
// means the steady-state step-time floor is L_dram/14 (~70-100cyc) instead of
// L/6 (~250cyc) at S=8. LDS consumers double-buffered one step ahead.
// Per-thread ring only -> no __syncthreads anywhere.
// ---------------------------------------------------------------------------
__global__ void __launch_bounds__(32) scan_kernel(
    const float* __restrict__ rk,       // [3][9]
    const float* __restrict__ dense_w,  // [3][1]
    const float* __restrict__ dense_b)  // [1]
{
    __shared__ float4 ring[S][3][32];   // 24 KB

    const int tid = threadIdx.x;
    const int b = blockIdx.x * 32 + tid;

    // z/r columns (0..5) pre-halved to match pre-halved xz/xr.
    float rkv[3][9];
#pragma unroll
    for (int u = 0; u < 3; u++)
#pragma unroll
        for (int j = 0; j < 9; j++) {
            float v = __ldg(rk + u * 9 + j);
            rkv[u][j] = (j < 6) ? 0.5f * v : v;
        }

    // packed weight pairs: columns (0,1),(2,3),(4,5),(6,7); column 8 scalar
    u64 Wp[3][4];
    float W8[3];
#pragma unroll
    for (int u = 0; u < 3; u++) {
#pragma unroll
        for (int p = 0; p < 4; p++)
            Wp[u][p] = pk(rkv[u][2 * p], rkv[u][2 * p + 1]);
        W8[u] = rkv[u][8];
    }

    // dense_w pre-doubled: out = halfm * dot(h, 2w) + db == m*dot(h,w)+db
    const float w0 = 2.0f * __ldg(dense_w);
    const float w1 = 2.0f * __ldg(dense_w + 1);
    const float w2 = 2.0f * __ldg(dense_w + 2);
    const float db = __ldg(dense_b);

    float h0 = 0.0f, h1 = 0.0f, h2 = 0.0f;

    // smem lane addresses
    u32 rz[S], rr[S], rh[S];
#pragma unroll
    for (int d = 0; d < S; d++) {
        rz[d] = smem_u32(&ring[d][0][tid]);
        rr[d] = smem_u32(&ring[d][1][tid]);
        rh[d] = smem_u32(&ring[d][2][tid]);
    }

    // prologue: fill all S stages (steps 0..S-1), one commit group per stage
#pragma unroll
    for (int d = 0; d < S; d++) {
        const size_t o = (size_t)d * Bb + b;
        cp16(rz[d], &g_bufZ[o]);
        cp16(rr[d], &g_bufR[o]);
        cp16(rh[d], &g_bufH[o]);
        cp_commit();
    }

    // next := data for step 0
    cp_wait<S - 1>();   // >=1 group done -> stage 0 resident
    float4 nz = ring[0][0][tid];
    float4 nr = ring[0][1][tid];
    float4 nh = ring[0][2][tid];

    for (int t = 0; t < Tt; t += 2) {
#pragma unroll
        for (int i = 0; i < 2; i++) {
            const int tc = t + i;
            const int cs = tc & (S - 1);         // current stage
            const int ns = (tc + 1) & (S - 1);   // next stage

            const float4 vz = nz;
            const float4 vr = nr;
            const float4 vh = nh;

            // Wait until stage (tc+1) is resident, then LDS into 'next'
            // (consumed next iteration -> full step of slack over LDS lat 29).
            cp_wait<S - 2>();
            nz = *reinterpret_cast<float4*>((char*)ring + (ns * 3 + 0) * 512 + tid * 16);
            nr = *reinterpret_cast<float4*>((char*)ring + (ns * 3 + 1) * 512 + tid * 16);
            nh = *reinterpret_cast<float4*>((char*)ring + (ns * 3 + 2) * 512 + tid * 16);

            // refill current stage with step tc+S (padded region covers tail);
            // cur was LDS'd from this stage one step ago -> safe to overwrite.
            {
                const size_t o = (size_t)(tc + S) * Bb + b;
                cp16(rz[cs], &g_bufZ[o]);
                cp16(rr[cs], &g_bufR[o]);
                cp16(rh[cs], &g_bufH[o]);
                cp_commit();
            }

            // ---- GRU step ----
            const u64 h0x = pk(h0, h0);
            const u64 h1x = pk(h1, h1);
            const u64 h2x = pk(h2, h2);

            u64 a01  = fma2(h2x, Wp[2][0], fma2(h1x, Wp[1][0], fma2(h0x, Wp[0][0], pk(vz.x, vz.y))));
            u64 a2r0 = fma2(h2x, Wp[2][1], fma2(h1x, Wp[1][1], fma2(h0x, Wp[0][1], pk(vz.z, vr.x))));
            u64 a45  = fma2(h2x, Wp[2][2], fma2(h1x, Wp[1][2], fma2(h0x, Wp[0][2], pk(vr.y, vr.z))));
            u64 hh01 = fma2(h2x, Wp[2][3], fma2(h1x, Wp[1][3], mul2(h0x, Wp[0][3])));
            float hh2 = fmaf(h2, W8[2], fmaf(h1, W8[1], h0 * W8[0]));

            float az0, az1, az2, ar0, ar1, ar2, hh0, hh1;
            upk(a01, az0, az1);
            upk(a2r0, az2, ar0);
            upk(a45, ar1, ar2);
            upk(hh01, hh0, hh1);

            const float tz0 = tanh_fast(az0);
            const float tz1 = tanh_fast(az1);
            const float tz2 = tanh_fast(az2);
            const float tr0 = tanh_fast(ar0);
            const float tr1 = tanh_fast(ar1);
            const float tr2 = tanh_fast(ar2);

            const float halfm = vz.w;  // 0.5*mask

            // g = m*(1-z) = halfm*(1 - tanh(a_z/2))
            const float g0 = fmaf(-halfm, tz0, halfm);
            const float g1 = fmaf(-halfm, tz1, halfm);
            const float g2 = fmaf(-halfm, tz2, halfm);

            // r = 0.5 + 0.5*tanh(a_r/2)
            const float r0 = fmaf(tr0, 0.5f, 0.5f);
            const float r1 = fmaf(tr1, 0.5f, 0.5f);
            const float r2 = fmaf(tr2, 0.5f, 0.5f);

            const float hc0 = tanh_fast(fmaf(r0, hh0, vh.x));
            const float hc1 = tanh_fast(fmaf(r1, hh1, vh.y));
            const float hc2 = tanh_fast(fmaf(r2, hh2, vh.z));

            // h_new = h + g*(hc - h)
            h0 = fmaf(g0, hc0 - h0, h0);
            h1 = fmaf(g1, hc1 - h1, h1);
            h2 = fmaf(g2, hc2 - h2, h2);

            // out = halfm * dot(h_new, 2w) + db
            const float dot = fmaf(h2, w2, fmaf(h1, w1, h0 * w0));
            g_outT[(size_t)tc * Bb + b] = fmaf(halfm, dot, db);
        }
    }
}

// ---------------------------------------------------------------------------
// Kernel C: transpose g_outT[t][b] -> out[b][t]
// ---------------------------------------------------------------------------
__global__ void transpose_kernel(float* __restrict__ out) {
    __shared__ float tile[32][33];
    const int bBase = blockIdx.x * 32;
    const int tBase = blockIdx.y * 32;

    tile[threadIdx.y][threadIdx.x] =
        g_outT[(size_t)(tBase + threadIdx.y) * Bb + (bBase + threadIdx.x)];
    __syncthreads();
    out[(size_t)(bBase + threadIdx.y) * Tt + (tBase + threadIdx.x)] =
        tile[threadIdx.x][threadIdx.y];
}

// ---------------------------------------------------------------------------
extern "C" void kernel_launch(void* const* d_in, const int* in_sizes, int n_in,
                              void* d_out, int out_size) {
    const float* x       = (const float*)d_in[0];  // (B,T,8)
    const float* kern    = (const float*)d_in[1];  // (8,9)
    const float* rk      = (const float*)d_in[2];  // (3,9)
    const float* bias_i  = (const float*)d_in[3];  // (9,)
    const float* bias_r  = (const float*)d_in[4];  // (9,)
    const float* dense_w = (const float*)d_in[5];  // (3,1)
    const float* dense_b = (const float*)d_in[6];  // (1,)
    float* out = (float*)d_out;                    // (B,T,1)

    (void)in_sizes; (void)n_in; (void)out_size;

    dim3 gA(Bb / 256, Tt / 8);
    prep_kernel<<<gA, 256>>>(x, kern, bias_i, bias_r);

    scan_kernel<<<Bb / 32, 32>>>(rk, dense_w, dense_b);

    dim3 gC(Bb / 32, Tt / 32);
    transpose_kernel<<<gC, dim3(32, 32)>>>(out);
}

// round 12
// speedup vs baseline: 1.2508x; 1.2508x over previous
#include <cuda_runtime.h>
#include <cuda_bf16.h>
#include <cstdint>

// Problem constants
#define Bb 2048
#define Tt 2048
#define S  16  // SMEM ring steps (4 chunks x 4 steps); buffers padded by S steps
#define C  4   // steps per chunk / commit group
// F=8, U=3, 3U=9

// Scratch: __device__ globals (allocation-free rule). Padded by S steps so
// ALL pipeline loads are unconditional and in-bounds.
__device__ float4 g_bufZ[(size_t)(Tt + S) * Bb];  // {.5*xz0,.5*xz1,.5*xz2, .5*mask}
__device__ float4 g_bufR[(size_t)(Tt + S) * Bb];  // {.5*xr0,.5*xr1,.5*xr2, 0}
__device__ float4 g_bufH[(size_t)(Tt + S) * Bb];  // {xh0, xh1, xh2, 0}
__device__ float  g_outT[(size_t)Tt * Bb];        // out in [t][b] layout

typedef unsigned long long u64;
typedef unsigned int u32;

// HW tanh (sm_75+): 1 MUFU op, rel err ~2^-11
__device__ __forceinline__ float tanh_fast(float x) {
    float y;
    asm("tanh.approx.f32 %0, %1;" : "=f"(y) : "f"(x));
    return y;
}

// f32x2 packed helpers (Blackwell FFMA2 — ptxas never auto-fuses from C++)
__device__ __forceinline__ u64 pk(float lo, float hi) {
    u64 r;
    asm("mov.b64 %0, {%1,%2};" : "=l"(r) : "f"(lo), "f"(hi));
    return r;
}
__device__ __forceinline__ void upk(u64 v, float& lo, float& hi) {
    asm("mov.b64 {%0,%1}, %2;" : "=f"(lo), "=f"(hi) : "l"(v));
}
__device__ __forceinline__ u64 fma2(u64 a, u64 b, u64 c) {
    u64 d;
    asm("fma.rn.f32x2 %0, %1, %2, %3;" : "=l"(d) : "l"(a), "l"(b), "l"(c));
    return d;
}
__device__ __forceinline__ u64 mul2(u64 a, u64 b) {
    u64 d;
    asm("mul.rn.f32x2 %0, %1, %2;" : "=l"(d) : "l"(a), "l"(b));
    return d;
}

// cp.async 16B: completion via commit-group counters
__device__ __forceinline__ void cp16(u32 smem_dst, const void* gsrc) {
    asm volatile("cp.async.cg.shared.global [%0], [%1], 16;"
                 :: "r"(smem_dst), "l"(gsrc) : "memory");
}
__device__ __forceinline__ void cp_commit() {
    asm volatile("cp.async.commit_group;" ::: "memory");
}
template <int N>
__device__ __forceinline__ void cp_wait() {
    asm volatile("cp.async.wait_group %0;" :: "n"(N) : "memory");
}

__device__ __forceinline__ u32 smem_u32(const void* p) {
    u32 a;
    asm("{ .reg .u64 t; cvta.to.shared.u64 t, %1; cvt.u32.u64 %0, t; }"
        : "=r"(a) : "l"(p));
    return a;
}

// ---------------------------------------------------------------------------
// Kernel A: input projection + mask -> [t][b]-major packed tiles.
// z/r pre-activations stored PRE-HALVED; mask stored as 0.5*m.
// ---------------------------------------------------------------------------
__global__ void __launch_bounds__(256) prep_kernel(
    const float* __restrict__ x,       // [B][T][8]
    const float* __restrict__ kern,    // [8][9]
    const float* __restrict__ bias_i,  // [9]
    const float* __restrict__ bias_r)  // [9]
{
    const int b  = blockIdx.x * 256 + threadIdx.x;
    const int t0 = blockIdx.y * 8;

    float bs[9];
#pragma unroll
    for (int j = 0; j < 9; j++) bs[j] = __ldg(bias_i + j) + __ldg(bias_r + j);
    float wv[8][9];
#pragma unroll
    for (int f = 0; f < 8; f++)
#pragma unroll
        for (int j = 0; j < 9; j++) wv[f][j] = __ldg(kern + f * 9 + j);

    const float4* x4 = reinterpret_cast<const float4*>(x) + (size_t)b * (Tt * 2);

#pragma unroll
    for (int i = 0; i < 8; i++) {
        const int t = t0 + i;
        float4 a = __ldg(x4 + (size_t)t * 2);
        float4 c = __ldg(x4 + (size_t)t * 2 + 1);
        float xf[8] = {a.x, a.y, a.z, a.w, c.x, c.y, c.z, c.w};

        float m = 0.0f;
#pragma unroll
        for (int f = 0; f < 8; f++)
            if (xf[f] != 0.0f) m = 0.5f;   // store 0.5*mask

        float acc[9];
#pragma unroll
        for (int j = 0; j < 9; j++) {
            float s = bs[j];
#pragma unroll
            for (int f = 0; f < 8; f++) s = fmaf(xf[f], wv[f][j], s);
            acc[j] = s;
        }

        const size_t o = (size_t)t * Bb + b;
        g_bufZ[o] = make_float4(0.5f * acc[0], 0.5f * acc[1], 0.5f * acc[2], m);
        g_bufR[o] = make_float4(0.5f * acc[3], 0.5f * acc[4], 0.5f * acc[5], 0.0f);
        g_bufH[o] = make_float4(acc[6], acc[7], acc[8], 0.0f);
    }
}

// ---------------------------------------------------------------------------
// Kernel B: sequential GRU scan, 64 blocks x 32 threads = 2048 lanes.
// cp.async SMEM ring, 4 chunks x 4 steps. ONE wait_group + ONE commit per
// 4-step chunk (wait_group costs ~90-150cyc regardless of readiness, so it
// must be amortized). Inner steps run wait-free on resident stages with the
// LDS double-buffer. Per-thread ring only -> no __syncthreads anywhere.
// ---------------------------------------------------------------------------
__global__ void __launch_bounds__(32) scan_kernel(
    const float* __restrict__ rk,       // [3][9]
    const float* __restrict__ dense_w,  // [3][1]
    const float* __restrict__ dense_b)  // [1]
{
    __shared__ float4 ring[S][3][32];   // 24 KB

    const int tid = threadIdx.x;
    const int b = blockIdx.x * 32 + tid;

    // z/r columns (0..5) pre-halved to match pre-halved xz/xr.
    float rkv[3][9];
#pragma unroll
    for (int u = 0; u < 3; u++)
#pragma unroll
        for (int j = 0; j < 9; j++) {
            float v = __ldg(rk + u * 9 + j);
            rkv[u][j] = (j < 6) ? 0.5f * v : v;
        }

    // packed weight pairs: columns (0,1),(2,3),(4,5),(6,7); column 8 scalar
    u64 Wp[3][4];
    float W8[3];
#pragma unroll
    for (int u = 0; u < 3; u++) {
#pragma unroll
        for (int p = 0; p < 4; p++)
            Wp[u][p] = pk(rkv[u][2 * p], rkv[u][2 * p + 1]);
        W8[u] = rkv[u][8];
    }

    // dense_w pre-doubled: out = halfm * dot(h, 2w) + db == m*dot(h,w)+db
    const float w0 = 2.0f * __ldg(dense_w);
    const float w1 = 2.0f * __ldg(dense_w + 1);
    const float w2 = 2.0f * __ldg(dense_w + 2);
    const float db = __ldg(dense_b);

    float h0 = 0.0f, h1 = 0.0f, h2 = 0.0f;

    // smem lane addresses per stage
    u32 rz[S], rr[S], rh[S];
#pragma unroll
    for (int d = 0; d < S; d++) {
        rz[d] = smem_u32(&ring[d][0][tid]);
        rr[d] = smem_u32(&ring[d][1][tid]);
        rh[d] = smem_u32(&ring[d][2][tid]);
    }

    // prologue: 4 chunk-groups (steps 0..15), one commit per chunk
#pragma unroll
    for (int c = 0; c < S / C; c++) {
#pragma unroll
        for (int s = 0; s < C; s++) {
            const int st = c * C + s;
            const size_t o = (size_t)st * Bb + b;
            cp16(rz[st], &g_bufZ[o]);
            cp16(rr[st], &g_bufR[o]);
            cp16(rh[st], &g_bufH[o]);
        }
        cp_commit();
    }

    // chunk 0 resident: committed=4, need group0 -> pending<=3
    cp_wait<3>();
    float4 nz = ring[0][0][tid];
    float4 nr = ring[0][1][tid];
    float4 nh = ring[0][2][tid];

    for (int c = 0; c < Tt / C; c++) {
        const int base = c * C;
#pragma unroll
        for (int s = 0; s < C; s++) {
            const int tc = base + s;
            const int ns = (tc + 1) & (S - 1);   // next stage

            const float4 vz = nz;
            const float4 vr = nr;
            const float4 vh = nh;

            // At the chunk boundary (s==C-1) the next LDS targets chunk c+1:
            // committed = 4+c groups, need group c+1 done -> pending <= 2.
            if (s == C - 1) cp_wait<2>();

            nz = *reinterpret_cast<float4*>((char*)ring + (ns * 3 + 0) * 512 + tid * 16);
            nr = *reinterpret_cast<float4*>((char*)ring + (ns * 3 + 1) * 512 + tid * 16);
            nh = *reinterpret_cast<float4*>((char*)ring + (ns * 3 + 2) * 512 + tid * 16);

            // After the last consume of this chunk's slot, refill it with
            // chunk c+4 (padded region covers the tail: max step 2063 < 2064).
            if (s == C - 1) {
                const int slot = c & 3;
#pragma unroll
                for (int q = 0; q < C; q++) {
                    const int st = slot * C + q;
                    const size_t o = (size_t)(base + S + q) * Bb + b;
                    cp16(rz[st], &g_bufZ[o]);
                    cp16(rr[st], &g_bufR[o]);
                    cp16(rh[st], &g_bufH[o]);
                }
                cp_commit();
            }

            // ---- GRU step ----
            const u64 h0x = pk(h0, h0);
            const u64 h1x = pk(h1, h1);
            const u64 h2x = pk(h2, h2);

            u64 a01  = fma2(h2x, Wp[2][0], fma2(h1x, Wp[1][0], fma2(h0x, Wp[0][0], pk(vz.x, vz.y))));
            u64 a2r0 = fma2(h2x, Wp[2][1], fma2(h1x, Wp[1][1], fma2(h0x, Wp[0][1], pk(vz.z, vr.x))));
            u64 a45  = fma2(h2x, Wp[2][2], fma2(h1x, Wp[1][2], fma2(h0x, Wp[0][2], pk(vr.y, vr.z))));
            u64 hh01 = fma2(h2x, Wp[2][3], fma2(h1x, Wp[1][3], mul2(h0x, Wp[0][3])));
            float hh2 = fmaf(h2, W8[2], fmaf(h1, W8[1], h0 * W8[0]));

            float az0, az1, az2, ar0, ar1, ar2, hh0, hh1;
            upk(a01, az0, az1);
            upk(a2r0, az2, ar0);
            upk(a45, ar1, ar2);
            upk(hh01, hh0, hh1);

            const float tz0 = tanh_fast(az0);
            const float tz1 = tanh_fast(az1);
            const float tz2 = tanh_fast(az2);
            const float tr0 = tanh_fast(ar0);
            const float tr1 = tanh_fast(ar1);
            const float tr2 = tanh_fast(ar2);

            const float halfm = vz.w;  // 0.5*mask

            // g = m*(1-z) = halfm*(1 - tanh(a_z/2))
            const float g0 = fmaf(-halfm, tz0, halfm);
            const float g1 = fmaf(-halfm, tz1, halfm);
            const float g2 = fmaf(-halfm, tz2, halfm);

            // r = 0.5 + 0.5*tanh(a_r/2)
            const float r0 = fmaf(tr0, 0.5f, 0.5f);
            const float r1 = fmaf(tr1, 0.5f, 0.5f);
            const float r2 = fmaf(tr2, 0.5f, 0.5f);

            const float hc0 = tanh_fast(fmaf(r0, hh0, vh.x));
            const float hc1 = tanh_fast(fmaf(r1, hh1, vh.y));
            const float hc2 = tanh_fast(fmaf(r2, hh2, vh.z));

            // h_new = h + g*(hc - h)
            h0 = fmaf(g0, hc0 - h0, h0);
            h1 = fmaf(g1, hc1 - h1, h1);
            h2 = fmaf(g2, hc2 - h2, h2);

            // out = halfm * dot(h_new, 2w) + db
            const float dot = fmaf(h2, w2, fmaf(h1, w1, h0 * w0));
            g_outT[(size_t)tc * Bb + b] = fmaf(halfm, dot, db);
        }
    }
}

// ---------------------------------------------------------------------------
// Kernel C: transpose g_outT[t][b] -> out[b][t]
// ---------------------------------------------------------------------------
__global__ void transpose_kernel(float* __restrict__ out) {
    __shared__ float tile[32][33];
    const int bBase = blockIdx.x * 32;
    const int tBase = blockIdx.y * 32;

    tile[threadIdx.y][threadIdx.x] =
        g_outT[(size_t)(tBase + threadIdx.y) * Bb + (bBase + threadIdx.x)];
    __syncthreads();
    out[(size_t)(bBase + threadIdx.y) * Tt + (tBase + threadIdx.x)] =
        tile[threadIdx.x][threadIdx.y];
}

// ---------------------------------------------------------------------------
extern "C" void kernel_launch(void* const* d_in, const int* in_sizes, int n_in,
                              void* d_out, int out_size) {
    const float* x       = (const float*)d_in[0];  // (B,T,8)
    const float* kern    = (const float*)d_in[1];  // (8,9)
    const float* rk      = (const float*)d_in[2];  // (3,9)
    const float* bias_i  = (const float*)d_in[3];  // (9,)
    const float* bias_r  = (const float*)d_in[4];  // (9,)
    const float* dense_w = (const float*)d_in[5];  // (3,1)
    const float* dense_b = (const float*)d_in[6];  // (1,)
    float* out = (float*)d_out;                    // (B,T,1)

    (void)in_sizes; (void)n_in; (void)out_size;

    dim3 gA(Bb / 256, Tt / 8);
    prep_kernel<<<gA, 256>>>(x, kern, bias_i, bias_r);

    scan_kernel<<<Bb / 32, 32>>>(rk, dense_w, dense_b);

    dim3 gC(Bb / 32, Tt / 32);
    transpose_kernel<<<gC, dim3(32, 32)>>>(out);
}